// round 16
// baseline (speedup 1.0000x reference)
#include <cuda_runtime.h>
#include <cuda_bf16.h>
#include <stdint.h>
#include <math.h>

#define NN 50000
#define NE 800000
#define SCAN_CHUNK 4096
#define NBLK ((NN + SCAN_CHUNK - 1) / SCAN_CHUNK)   // 13

// ---------------- scratch (device globals: no allocation allowed) ----------
__device__ int   g_is64;
__device__ int   g_deg[NN];
__device__ int   g_off[NN + 1];
__device__ int   g_cur[NN];
__device__ int   g_bsum[NBLK];
__device__ int   g_bpre[NBLK];
__device__ int   g_src[NE];
__device__ __align__(16) float g_w[NE];
__device__ __align__(16) float g_bufA[NN * 256];   // agg128 / agg32 / xl
__device__ __align__(16) float g_bufB[NN * 256];   // xr
__device__ __align__(16) float g_h1[NN * 32];
__device__ __align__(16) float g_h2[NN * 32];
__device__ __align__(16) float g_h3[NN * 256];
__device__ __align__(16) float g_h4[NN * 256];
// packed bf16x2 hi/lo copies for tensor-core GEMMs
__device__ __align__(16) uint32_t g_ah[NN * 128];
__device__ __align__(16) uint32_t g_al[NN * 128];
__device__ __align__(16) uint32_t g_wh[2 * 128 * 256];
__device__ __align__(16) uint32_t g_wl[2 * 128 * 256];

// Buffer selectors: resolve device-global scratch at compile time. S==-1 -> ext.
template <int S>
__device__ __forceinline__ const float* SB(const float* ext) {
    if constexpr (S == 0) return g_bufA;
    else if constexpr (S == 1) return g_bufB;
    else if constexpr (S == 2) return g_h1;
    else if constexpr (S == 3) return g_h2;
    else if constexpr (S == 4) return g_h3;
    else if constexpr (S == 5) return g_h4;
    else return ext;
}
template <int S>
__device__ __forceinline__ float* SBo(float* ext) {
    if constexpr (S == 0) return g_bufA;
    else if constexpr (S == 1) return g_bufB;
    else if constexpr (S == 2) return g_h1;
    else if constexpr (S == 3) return g_h2;
    else if constexpr (S == 4) return g_h3;
    else if constexpr (S == 5) return g_h4;
    else return ext;
}

// ---------------- helpers ----------------
__device__ __forceinline__ float lrelu(float v) { return v > 0.f ? v : 0.2f * v; }
__device__ __forceinline__ float elu(float v)  { return v > 0.f ? v : __expf(v) - 1.f; }

__device__ __forceinline__ int clampN(int v) {
    return v < 0 ? 0 : (v >= NN ? NN - 1 : v);
}
__device__ __forceinline__ int load_idx(const void* ei, size_t pos, int is64) {
    if (is64) return clampN((int)((const long long*)ei)[pos]);
    return clampN(((const int*)ei)[pos]);
}

static __device__ __forceinline__ uint32_t pack2(__nv_bfloat16 a, __nv_bfloat16 b) {
    return (uint32_t)__bfloat16_as_ushort(a) | ((uint32_t)__bfloat16_as_ushort(b) << 16);
}
static __device__ __forceinline__ void split2(float2 u, uint32_t& hi, uint32_t& lo) {
    __nv_bfloat16 hx = __float2bfloat16(u.x);
    __nv_bfloat16 hy = __float2bfloat16(u.y);
    hi = pack2(hx, hy);
    lo = pack2(__float2bfloat16(u.x - __bfloat162float(hx)),
               __float2bfloat16(u.y - __bfloat162float(hy)));
}

// mma.sync m16n8k16 row.col f32.bf16.bf16.f32 (legacy tensor path, sm_80+)
#define MMA_BF16(d, a, b0v, b1v) \
    asm volatile("mma.sync.aligned.m16n8k16.row.col.f32.bf16.bf16.f32 " \
        "{%0,%1,%2,%3}, {%4,%5,%6,%7}, {%8,%9}, {%0,%1,%2,%3};" \
        : "+f"((d)[0]), "+f"((d)[1]), "+f"((d)[2]), "+f"((d)[3]) \
        : "r"((a)[0]), "r"((a)[1]), "r"((a)[2]), "r"((a)[3]), "r"(b0v), "r"(b1v))

// ---------------- dtype detection ----------------
__global__ void k_detect(const int* __restrict__ ei32) {
    if (threadIdx.x == 0 && blockIdx.x == 0) {
        int allzero = 1;
        #pragma unroll 1
        for (int i = 0; i < 64; i++)
            if (ei32[2 * i + 1] != 0) { allzero = 0; break; }
        g_is64 = allzero;
    }
}

// ---------------- CSR build ----------------
__global__ void k_zero_deg() {
    int i = blockIdx.x * blockDim.x + threadIdx.x;
    if (i < NN) g_deg[i] = 0;
}

__global__ void k_count(const void* __restrict__ ei) {
    int e = blockIdx.x * blockDim.x + threadIdx.x;
    if (e < NE) {
        int dst = load_idx(ei, (size_t)NE + e, g_is64);
        atomicAdd(&g_deg[dst], 1);
    }
}

__global__ __launch_bounds__(1024) void k_scan_local() {
    __shared__ int ws[32];
    int b = blockIdx.x, t = threadIdx.x;
    int base = b * SCAN_CHUNK + t * 4;
    int v[4];
    #pragma unroll
    for (int c = 0; c < 4; c++) v[c] = (base + c < NN) ? g_deg[base + c] : 0;
    int s = v[0] + v[1] + v[2] + v[3];
    int x = s;
    #pragma unroll
    for (int o = 1; o < 32; o <<= 1) {
        int y = __shfl_up_sync(0xffffffffu, x, o);
        if ((t & 31) >= o) x += y;
    }
    if ((t & 31) == 31) ws[t >> 5] = x;
    __syncthreads();
    if (t < 32) {
        int w = ws[t];
        #pragma unroll
        for (int o = 1; o < 32; o <<= 1) {
            int y = __shfl_up_sync(0xffffffffu, w, o);
            if (t >= o) w += y;
        }
        ws[t] = w;
    }
    __syncthreads();
    int incl = x + ((t >= 32) ? ws[(t >> 5) - 1] : 0);
    int run = incl - s;
    #pragma unroll
    for (int c = 0; c < 4; c++) {
        if (base + c < NN) g_off[base + c] = run;
        run += v[c];
    }
    if (t == 1023) g_bsum[b] = incl;
}

__global__ void k_scan_bsum() {
    int t = threadIdx.x;
    int v = (t < NBLK) ? g_bsum[t] : 0;
    int x = v;
    #pragma unroll
    for (int o = 1; o < 32; o <<= 1) {
        int y = __shfl_up_sync(0xffffffffu, x, o);
        if (t >= o) x += y;
    }
    if (t < NBLK) g_bpre[t] = x - v;
    if (t == 31) g_off[NN] = x;
}

__global__ void k_scan_add() {
    int i = blockIdx.x * blockDim.x + threadIdx.x;
    if (i < NN) {
        int o = g_off[i] + g_bpre[i / SCAN_CHUNK];
        g_off[i] = o;
        g_cur[i] = o;
    }
}

__global__ void k_scatter(const void* __restrict__ ei, const float* __restrict__ ea) {
    int e = blockIdx.x * blockDim.x + threadIdx.x;
    if (e < NE) {
        int is64 = g_is64;
        int s = load_idx(ei, (size_t)e, is64);
        int d = load_idx(ei, (size_t)NE + e, is64);
        int p = atomicAdd(&g_cur[d], 1);
        if (p >= 0 && p < NE) {
            g_src[p] = s;
            g_w[p]   = ea[e];
        }
    }
}

// ---------------- GraphConv max aggregation (warp per node, unroll-4) ------
template <int F, int XSEL>
__global__ void k_gc_agg(const float* __restrict__ xext) {
    const float* __restrict__ x = SB<XSEL>(xext);
    float* __restrict__ agg = g_bufA;
    int node = (blockIdx.x * blockDim.x + threadIdx.x) >> 5;
    int lane = threadIdx.x & 31;
    if (node >= NN) return;
    int beg = g_off[node], end = g_off[node + 1];
    if constexpr (F == 128) {
        float4 mx = make_float4(-INFINITY, -INFINITY, -INFINITY, -INFINITY);
        int j = beg;
        for (; j + 3 < end; j += 4) {
            int   s0 = g_src[j],   s1 = g_src[j+1], s2 = g_src[j+2], s3 = g_src[j+3];
            float w0 = g_w[j],     w1 = g_w[j+1],   w2 = g_w[j+2],   w3 = g_w[j+3];
            float4 v0 = *(const float4*)&x[(size_t)s0 * 128 + lane * 4];
            float4 v1 = *(const float4*)&x[(size_t)s1 * 128 + lane * 4];
            float4 v2 = *(const float4*)&x[(size_t)s2 * 128 + lane * 4];
            float4 v3 = *(const float4*)&x[(size_t)s3 * 128 + lane * 4];
            mx.x = fmaxf(mx.x, fmaxf(fmaxf(v0.x*w0, v1.x*w1), fmaxf(v2.x*w2, v3.x*w3)));
            mx.y = fmaxf(mx.y, fmaxf(fmaxf(v0.y*w0, v1.y*w1), fmaxf(v2.y*w2, v3.y*w3)));
            mx.z = fmaxf(mx.z, fmaxf(fmaxf(v0.z*w0, v1.z*w1), fmaxf(v2.z*w2, v3.z*w3)));
            mx.w = fmaxf(mx.w, fmaxf(fmaxf(v0.w*w0, v1.w*w1), fmaxf(v2.w*w2, v3.w*w3)));
        }
        for (; j < end; j++) {
            int s = g_src[j];
            float w = g_w[j];
            float4 v = *(const float4*)&x[(size_t)s * 128 + lane * 4];
            mx.x = fmaxf(mx.x, v.x * w);
            mx.y = fmaxf(mx.y, v.y * w);
            mx.z = fmaxf(mx.z, v.z * w);
            mx.w = fmaxf(mx.w, v.w * w);
        }
        if (beg == end) mx = make_float4(0.f, 0.f, 0.f, 0.f);
        *(float4*)&agg[(size_t)node * 128 + lane * 4] = mx;
    } else {
        float mx = -INFINITY;
        int j = beg;
        for (; j + 3 < end; j += 4) {
            int   s0 = g_src[j],   s1 = g_src[j+1], s2 = g_src[j+2], s3 = g_src[j+3];
            float w0 = g_w[j],     w1 = g_w[j+1],   w2 = g_w[j+2],   w3 = g_w[j+3];
            float a = x[(size_t)s0 * 32 + lane] * w0;
            float b = x[(size_t)s1 * 32 + lane] * w1;
            float c = x[(size_t)s2 * 32 + lane] * w2;
            float d = x[(size_t)s3 * 32 + lane] * w3;
            mx = fmaxf(mx, fmaxf(fmaxf(a, b), fmaxf(c, d)));
        }
        for (; j < end; j++) mx = fmaxf(mx, x[(size_t)g_src[j] * 32 + lane] * g_w[j]);
        agg[(size_t)node * 32 + lane] = (beg == end) ? 0.f : mx;
    }
}

// ---------------- GEMM, N-out = 32 (fp32; GC layers + final linear) -------
template <int K, int A1SEL, bool DUAL, int A2SEL, bool RELU, int CSEL>
__global__ __launch_bounds__(128)
void k_gemm_n32(const float* __restrict__ A1e, const float* __restrict__ B1,
                const float* __restrict__ A2e, const float* __restrict__ B2,
                const float* __restrict__ bias, float* __restrict__ Ce, int M) {
    const float* __restrict__ A1 = SB<A1SEL>(A1e);
    const float* __restrict__ A2 = SB<A2SEL>(A2e);
    float* __restrict__ C = SBo<CSEL>(Ce);

    __shared__ float As[32][128];
    __shared__ float A2s[32][128];
    __shared__ float Bs[32][32];
    __shared__ float B2s[32][32];

    int t  = threadIdx.x;
    int m0 = blockIdx.x * 128;
    int j0 = (t & 7) * 4;
    int r0 = (t >> 3) * 8;

    float acc[8][4];
    #pragma unroll
    for (int i = 0; i < 8; i++)
        #pragma unroll
        for (int c = 0; c < 4; c++) acc[i][c] = 0.f;

    for (int kb = 0; kb < K; kb += 32) {
        #pragma unroll
        for (int l = 0; l < 8; l++) {
            int slot = t + l * 128;
            int m = slot >> 3;
            int kq = slot & 7;
            int row = m0 + m;
            float4 v = make_float4(0.f, 0.f, 0.f, 0.f);
            if (row < M) v = *(const float4*)&A1[(size_t)row * K + kb + kq * 4];
            As[kq * 4 + 0][m] = v.x; As[kq * 4 + 1][m] = v.y;
            As[kq * 4 + 2][m] = v.z; As[kq * 4 + 3][m] = v.w;
            if constexpr (DUAL) {
                float4 v2 = make_float4(0.f, 0.f, 0.f, 0.f);
                if (row < M) v2 = *(const float4*)&A2[(size_t)row * K + kb + kq * 4];
                A2s[kq * 4 + 0][m] = v2.x; A2s[kq * 4 + 1][m] = v2.y;
                A2s[kq * 4 + 2][m] = v2.z; A2s[kq * 4 + 3][m] = v2.w;
            }
        }
        #pragma unroll
        for (int l = 0; l < 2; l++) {
            int slot = t + l * 128;
            int k = slot >> 3;
            int jq = slot & 7;
            *(float4*)&Bs[k][jq * 4] = *(const float4*)&B1[(size_t)(kb + k) * 32 + jq * 4];
            if constexpr (DUAL)
                *(float4*)&B2s[k][jq * 4] = *(const float4*)&B2[(size_t)(kb + k) * 32 + jq * 4];
        }
        __syncthreads();

        #pragma unroll
        for (int kk = 0; kk < 32; kk++) {
            float av[8], bv[4];
            *(float4*)&av[0] = *(float4*)&As[kk][r0];
            *(float4*)&av[4] = *(float4*)&As[kk][r0 + 4];
            *(float4*)&bv[0] = *(float4*)&Bs[kk][j0];
            #pragma unroll
            for (int i = 0; i < 8; i++)
                #pragma unroll
                for (int c = 0; c < 4; c++) acc[i][c] += av[i] * bv[c];
            if constexpr (DUAL) {
                float av2[8], bv2[4];
                *(float4*)&av2[0] = *(float4*)&A2s[kk][r0];
                *(float4*)&av2[4] = *(float4*)&A2s[kk][r0 + 4];
                *(float4*)&bv2[0] = *(float4*)&B2s[kk][j0];
                #pragma unroll
                for (int i = 0; i < 8; i++)
                    #pragma unroll
                    for (int c = 0; c < 4; c++) acc[i][c] += av2[i] * bv2[c];
            }
        }
        __syncthreads();
    }

    float bv[4];
    *(float4*)&bv[0] = *(const float4*)&bias[j0];
    #pragma unroll
    for (int i = 0; i < 8; i++) {
        int row = m0 + r0 + i;
        if (row < M) {
            float o[4];
            #pragma unroll
            for (int c = 0; c < 4; c++) {
                float v = acc[i][c] + bv[c];
                if constexpr (RELU) v = fmaxf(v, 0.f);
                o[c] = v;
            }
            *(float4*)&C[(size_t)row * 32 + j0] = *(float4*)&o[0];
        }
    }
}

// ---------------- bf16 split pre-conversion ---------------------------------
// A: [NN, KDIM] fp32 -> g_ah/g_al packed bf16x2 (KWT = KDIM/2 words per row)
template <int KDIM, int ASEL>
__global__ void k_conv_a(const float* __restrict__ xext) {
    constexpr int KWT = KDIM / 2;
    const float* __restrict__ A = SB<ASEL>(xext);
    int idx = blockIdx.x * blockDim.x + threadIdx.x;
    if (idx >= NN * KWT) return;
    int r = idx / KWT, w = idx - r * KWT;
    float2 u = *(const float2*)&A[(size_t)r * KDIM + 2 * w];
    uint32_t hi, lo;
    split2(u, hi, lo);
    g_ah[idx] = hi;
    g_al[idx] = lo;
}

// W: [KDIM, 256] fp32 (z=0: Wl, z=1: Wr) -> g_wh/g_wl  [z][KWT][256]
template <int KDIM>
__global__ void k_conv_w(const float* __restrict__ Wl, const float* __restrict__ Wr) {
    constexpr int KWT = KDIM / 2;
    int idx = blockIdx.x * blockDim.x + threadIdx.x;
    if (idx >= 2 * KWT * 256) return;
    int z = idx / (KWT * 256);
    int rem = idx - z * (KWT * 256);
    int w = rem >> 8, n = rem & 255;
    const float* W = z ? Wr : Wl;
    float2 u = make_float2(W[(size_t)(2 * w) * 256 + n], W[(size_t)(2 * w + 1) * 256 + n]);
    uint32_t hi, lo;
    split2(u, hi, lo);
    g_wh[idx] = hi;
    g_wl[idx] = lo;
}

// ---------------- mma.sync bf16 GEMM: xl/xr (N=256), 3-term split ----------
// Reads pre-converted g_ah/g_al and g_wh/g_wl; writes g_bufA (z=0) / g_bufB (z=1).
template <int KDIM>
__global__ __launch_bounds__(256)
void k_mma_gemm(const float* __restrict__ biasl, const float* __restrict__ biasr) {
    constexpr int KW = 16;
    constexpr int KWT = KDIM / 2;
    __shared__ uint32_t Ah[128][KW + 1], Al[128][KW + 1];
    __shared__ uint32_t Bh[128][KW + 1], Bq[128][KW + 1];

    int z = blockIdx.z;
    const float* __restrict__ bi = z ? biasr : biasl;
    float* __restrict__ C        = z ? g_bufB : g_bufA;

    int tid = threadIdx.x;
    int wid = tid >> 5, lane = tid & 31;
    int warp_m = wid & 3, warp_n = wid >> 2;
    int m0 = blockIdx.y * 128;
    int n0 = blockIdx.x * 128;
    int lg = lane >> 2, lq = lane & 3;

    float acc[2][8][4];
    #pragma unroll
    for (int mt = 0; mt < 2; mt++)
        #pragma unroll
        for (int nt = 0; nt < 8; nt++)
            #pragma unroll
            for (int c = 0; c < 4; c++) acc[mt][nt][c] = 0.f;

    for (int kb = 0; kb < KDIM; kb += 32) {
        int kbw = kb >> 1;
        #pragma unroll
        for (int i = 0; i < 8; i++) {
            int idx = tid + i * 256;
            int r = idx >> 4, w = idx & 15;
            int row = m0 + r;
            uint32_t vh = 0, vl = 0;
            if (row < NN) {
                size_t p = (size_t)row * KWT + kbw + w;
                vh = g_ah[p];
                vl = g_al[p];
            }
            Ah[r][w] = vh;
            Al[r][w] = vl;
        }
        #pragma unroll
        for (int i = 0; i < 8; i++) {
            int idx = tid + i * 256;
            int n = idx & 127, w = idx >> 7;
            size_t p = (size_t)z * KWT * 256 + (size_t)(kbw + w) * 256 + n0 + n;
            Bh[n][w] = g_wh[p];
            Bq[n][w] = g_wl[p];
        }
        __syncthreads();

        #pragma unroll
        for (int ks = 0; ks < 2; ks++) {
            int ws = ks * 8;
            uint32_t ah[2][4], al[2][4];
            #pragma unroll
            for (int mt = 0; mt < 2; mt++) {
                int r = warp_m * 32 + mt * 16 + lg;
                ah[mt][0] = Ah[r][ws + lq];     ah[mt][1] = Ah[r + 8][ws + lq];
                ah[mt][2] = Ah[r][ws + 4 + lq]; ah[mt][3] = Ah[r + 8][ws + 4 + lq];
                al[mt][0] = Al[r][ws + lq];     al[mt][1] = Al[r + 8][ws + lq];
                al[mt][2] = Al[r][ws + 4 + lq]; al[mt][3] = Al[r + 8][ws + 4 + lq];
            }
            #pragma unroll
            for (int nt = 0; nt < 8; nt++) {
                int cb = warp_n * 64 + nt * 8 + lg;
                uint32_t bh0 = Bh[cb][ws + lq], bh1 = Bh[cb][ws + 4 + lq];
                uint32_t bq0 = Bq[cb][ws + lq], bq1 = Bq[cb][ws + 4 + lq];
                #pragma unroll
                for (int mt = 0; mt < 2; mt++) {
                    MMA_BF16(acc[mt][nt], ah[mt], bh0, bh1);
                    MMA_BF16(acc[mt][nt], ah[mt], bq0, bq1);
                    MMA_BF16(acc[mt][nt], al[mt], bh0, bh1);
                }
            }
        }
        __syncthreads();
    }

    #pragma unroll
    for (int nt = 0; nt < 8; nt++) {
        int col = n0 + warp_n * 64 + nt * 8 + lq * 2;
        float b0 = bi[col], b1 = bi[col + 1];
        #pragma unroll
        for (int mt = 0; mt < 2; mt++) {
            int r0 = m0 + warp_m * 32 + mt * 16 + lg;
            if (r0 < NN) {
                float2 o = make_float2(acc[mt][nt][0] + b0, acc[mt][nt][1] + b1);
                *(float2*)&C[(size_t)r0 * 256 + col] = o;
            }
            if (r0 + 8 < NN) {
                float2 o = make_float2(acc[mt][nt][2] + b0, acc[mt][nt][3] + b1);
                *(float2*)&C[(size_t)(r0 + 8) * 256 + col] = o;
            }
        }
    }
}

// ---------------- GATv2: warp per node, 2-edge branch-free online softmax --
template <int OSEL>
__global__ void k_gat(const float* __restrict__ att, const float* __restrict__ bias) {
    const float* __restrict__ xl = g_bufA;
    const float* __restrict__ xr = g_bufB;
    float* __restrict__ out = SBo<OSEL>((float*)0);

    int node = (blockIdx.x * blockDim.x + threadIdx.x) >> 5;
    int lane = threadIdx.x & 31;
    if (node >= NN) return;
    int base = (lane >> 2) * 32 + (lane & 3) * 8;

    float4 at0 = *(const float4*)&att[base];
    float4 at1 = *(const float4*)&att[base + 4];
    float4 xr0 = *(const float4*)&xr[(size_t)node * 256 + base];
    float4 xr1 = *(const float4*)&xr[(size_t)node * 256 + base + 4];

    float m = -INFINITY, d = 0.f;
    float4 acc0 = make_float4(0.f, 0.f, 0.f, 0.f);
    float4 acc1 = make_float4(0.f, 0.f, 0.f, 0.f);

    int beg = g_off[node], end = g_off[node + 1];
    int T = end - beg + 1;
    int t = 0;
    for (; t + 1 < T; t += 2) {
        int i0 = beg + t, i1 = beg + t + 1;
        int s0 = g_src[i0];
        int s1 = (i1 < end) ? g_src[i1] : node;
        float4 a0 = *(const float4*)&xl[(size_t)s0 * 256 + base];
        float4 a1 = *(const float4*)&xl[(size_t)s0 * 256 + base + 4];
        float4 b0 = *(const float4*)&xl[(size_t)s1 * 256 + base];
        float4 b1 = *(const float4*)&xl[(size_t)s1 * 256 + base + 4];
        float sc0 = at0.x * lrelu(a0.x + xr0.x) + at0.y * lrelu(a0.y + xr0.y)
                  + at0.z * lrelu(a0.z + xr0.z) + at0.w * lrelu(a0.w + xr0.w)
                  + at1.x * lrelu(a1.x + xr1.x) + at1.y * lrelu(a1.y + xr1.y)
                  + at1.z * lrelu(a1.z + xr1.z) + at1.w * lrelu(a1.w + xr1.w);
        float sc1 = at0.x * lrelu(b0.x + xr0.x) + at0.y * lrelu(b0.y + xr0.y)
                  + at0.z * lrelu(b0.z + xr0.z) + at0.w * lrelu(b0.w + xr0.w)
                  + at1.x * lrelu(b1.x + xr1.x) + at1.y * lrelu(b1.y + xr1.y)
                  + at1.z * lrelu(b1.z + xr1.z) + at1.w * lrelu(b1.w + xr1.w);
        sc0 += __shfl_xor_sync(0xffffffffu, sc0, 1);
        sc0 += __shfl_xor_sync(0xffffffffu, sc0, 2);
        sc1 += __shfl_xor_sync(0xffffffffu, sc1, 1);
        sc1 += __shfl_xor_sync(0xffffffffu, sc1, 2);
        float nm = fmaxf(m, fmaxf(sc0, sc1));
        float r  = __expf(m - nm);
        float p0 = __expf(sc0 - nm);
        float p1 = __expf(sc1 - nm);
        d = d * r + p0 + p1;
        acc0.x = acc0.x * r + p0 * a0.x + p1 * b0.x;
        acc0.y = acc0.y * r + p0 * a0.y + p1 * b0.y;
        acc0.z = acc0.z * r + p0 * a0.z + p1 * b0.z;
        acc0.w = acc0.w * r + p0 * a0.w + p1 * b0.w;
        acc1.x = acc1.x * r + p0 * a1.x + p1 * b1.x;
        acc1.y = acc1.y * r + p0 * a1.y + p1 * b1.y;
        acc1.z = acc1.z * r + p0 * a1.z + p1 * b1.z;
        acc1.w = acc1.w * r + p0 * a1.w + p1 * b1.w;
        m = nm;
    }
    if (t < T) {
        int i0 = beg + t;
        int s = (i0 < end) ? g_src[i0] : node;
        float4 a0 = *(const float4*)&xl[(size_t)s * 256 + base];
        float4 a1 = *(const float4*)&xl[(size_t)s * 256 + base + 4];
        float sc = at0.x * lrelu(a0.x + xr0.x) + at0.y * lrelu(a0.y + xr0.y)
                 + at0.z * lrelu(a0.z + xr0.z) + at0.w * lrelu(a0.w + xr0.w)
                 + at1.x * lrelu(a1.x + xr1.x) + at1.y * lrelu(a1.y + xr1.y)
                 + at1.z * lrelu(a1.z + xr1.z) + at1.w * lrelu(a1.w + xr1.w);
        sc += __shfl_xor_sync(0xffffffffu, sc, 1);
        sc += __shfl_xor_sync(0xffffffffu, sc, 2);
        float nm = fmaxf(m, sc);
        float r  = __expf(m - nm);
        float p  = __expf(sc - nm);
        d = d * r + p;
        acc0.x = acc0.x * r + p * a0.x; acc0.y = acc0.y * r + p * a0.y;
        acc0.z = acc0.z * r + p * a0.z; acc0.w = acc0.w * r + p * a0.w;
        acc1.x = acc1.x * r + p * a1.x; acc1.y = acc1.y * r + p * a1.y;
        acc1.z = acc1.z * r + p * a1.z; acc1.w = acc1.w * r + p * a1.w;
    }

    float inv = 1.f / d;
    float4 b0 = *(const float4*)&bias[base];
    float4 b1 = *(const float4*)&bias[base + 4];
    float4 o0, o1;
    o0.x = elu(acc0.x * inv + b0.x); o0.y = elu(acc0.y * inv + b0.y);
    o0.z = elu(acc0.z * inv + b0.z); o0.w = elu(acc0.w * inv + b0.w);
    o1.x = elu(acc1.x * inv + b1.x); o1.y = elu(acc1.y * inv + b1.y);
    o1.z = elu(acc1.z * inv + b1.z); o1.w = elu(acc1.w * inv + b1.w);
    *(float4*)&out[(size_t)node * 256 + base]     = o0;
    *(float4*)&out[(size_t)node * 256 + base + 4] = o1;
}

// ---------------- launch ----------------
extern "C" void kernel_launch(void* const* d_in, const int* in_sizes, int n_in,
                              void* d_out, int out_size) {
    const float* x       = (const float*)d_in[0];
    const void*  ei      = d_in[1];
    const float* ea      = (const float*)d_in[2];
    const float* W_rel1  = (const float*)d_in[3];
    const float* b_rel1  = (const float*)d_in[4];
    const float* W_root1 = (const float*)d_in[5];
    const float* W_rel2  = (const float*)d_in[6];
    const float* b_rel2  = (const float*)d_in[7];
    const float* W_root2 = (const float*)d_in[8];
    const float* Wl1     = (const float*)d_in[9];
    const float* bl1     = (const float*)d_in[10];
    const float* Wr1     = (const float*)d_in[11];
    const float* br1     = (const float*)d_in[12];
    const float* att1    = (const float*)d_in[13];
    const float* bias1   = (const float*)d_in[14];
    const float* Wl2     = (const float*)d_in[15];
    const float* bl2     = (const float*)d_in[16];
    const float* Wr2     = (const float*)d_in[17];
    const float* br2     = (const float*)d_in[18];
    const float* att2    = (const float*)d_in[19];
    const float* bias2   = (const float*)d_in[20];
    const float* W_lin   = (const float*)d_in[21];
    const float* b_lin   = (const float*)d_in[22];
    float*       out     = (float*)d_out;

    const int M = NN;
    const int MT = (NN + 127) / 128;   // 391 M-tiles
    dim3 gmma(2, MT, 2);

    // dtype detection + CSR build
    k_detect<<<1, 32>>>((const int*)ei);
    k_zero_deg<<<(NN + 255) / 256, 256>>>();
    k_count<<<(NE + 255) / 256, 256>>>(ei);
    k_scan_local<<<NBLK, 1024>>>();
    k_scan_bsum<<<1, 32>>>();
    k_scan_add<<<(NN + 255) / 256, 256>>>();
    k_scatter<<<(NE + 255) / 256, 256>>>(ei, ea);

    // GraphConv 1: agg(x) -> g_bufA; h1 = relu(agg@W_rel1 + x@W_root1 + b)
    k_gc_agg<128, -1><<<(NN + 7) / 8, 256>>>(x);
    k_gemm_n32<128, 0, true, -1, true, 2><<<MT, 128>>>(
        (const float*)0, W_rel1, x, W_root1, b_rel1, (float*)0, M);

    // GraphConv 2: agg(h1) -> g_bufA; h2 = relu(agg@W_rel2 + h1@W_root2 + b)
    k_gc_agg<32, 2><<<(NN + 7) / 8, 256>>>((const float*)0);
    k_gemm_n32<32, 0, true, 2, true, 3><<<MT, 128>>>(
        (const float*)0, W_rel2, (const float*)0, W_root2, b_rel2, (float*)0, M);

    // GATv2 1: pre-convert h2 + W, xl/xr via mma bf16-split (K=32)
    k_conv_a<32, 3><<<(NN * 16 + 255) / 256, 256>>>((const float*)0);
    k_conv_w<32><<<(2 * 16 * 256 + 255) / 256, 256>>>(Wl1, Wr1);
    k_mma_gemm<32><<<gmma, 256>>>(bl1, br1);
    k_gat<4><<<(NN + 7) / 8, 256>>>(att1, bias1);

    // GATv2 2: pre-convert h3 + W, xl/xr via mma bf16-split (K=256)
    k_conv_a<256, 4><<<(NN * 128 + 255) / 256, 256>>>((const float*)0);
    k_conv_w<256><<<(2 * 128 * 256 + 255) / 256, 256>>>(Wl2, Wr2);
    k_mma_gemm<256><<<gmma, 256>>>(bl2, br2);
    k_gat<5><<<(NN + 7) / 8, 256>>>(att2, bias2);

    // Final linear: out = h4 @ W_lin + b_lin
    k_gemm_n32<256, 5, false, -1, false, -1><<<MT, 128>>>(
        (const float*)0, W_lin, (const float*)0, (const float*)0, b_lin, out, M);
}

// round 17
// speedup vs baseline: 1.0958x; 1.0958x over previous
#include <cuda_runtime.h>
#include <cuda_bf16.h>
#include <stdint.h>
#include <math.h>

#define NN 50000
#define NE 800000
#define SCAN_CHUNK 4096
#define NBLK ((NN + SCAN_CHUNK - 1) / SCAN_CHUNK)   // 13

// ---------------- scratch (device globals: no allocation allowed) ----------
__device__ int   g_is64;
__device__ int   g_deg[NN];
__device__ int   g_off[NN + 1];
__device__ int   g_cur[NN];
__device__ int   g_bsum[NBLK];
__device__ int   g_bpre[NBLK];
__device__ int   g_src[NE];
__device__ __align__(16) float g_w[NE];
__device__ __align__(16) float g_bufA[NN * 256];   // agg128 / agg32 / xl
__device__ __align__(16) float g_bufB[NN * 256];   // xr
__device__ __align__(16) float g_h1[NN * 32];
__device__ __align__(16) float g_h2[NN * 32];
__device__ __align__(16) float g_h3[NN * 256];
__device__ __align__(16) float g_h4[NN * 256];

// Buffer selectors: resolve device-global scratch at compile time. S==-1 -> ext.
template <int S>
__device__ __forceinline__ const float* SB(const float* ext) {
    if constexpr (S == 0) return g_bufA;
    else if constexpr (S == 1) return g_bufB;
    else if constexpr (S == 2) return g_h1;
    else if constexpr (S == 3) return g_h2;
    else if constexpr (S == 4) return g_h3;
    else if constexpr (S == 5) return g_h4;
    else return ext;
}
template <int S>
__device__ __forceinline__ float* SBo(float* ext) {
    if constexpr (S == 0) return g_bufA;
    else if constexpr (S == 1) return g_bufB;
    else if constexpr (S == 2) return g_h1;
    else if constexpr (S == 3) return g_h2;
    else if constexpr (S == 4) return g_h3;
    else if constexpr (S == 5) return g_h4;
    else return ext;
}

// ---------------- helpers ----------------
__device__ __forceinline__ float lrelu(float v) { return v > 0.f ? v : 0.2f * v; }
__device__ __forceinline__ float elu(float v)  { return v > 0.f ? v : __expf(v) - 1.f; }

__device__ __forceinline__ int clampN(int v) {
    return v < 0 ? 0 : (v >= NN ? NN - 1 : v);
}
__device__ __forceinline__ int load_idx(const void* ei, size_t pos, int is64) {
    if (is64) return clampN((int)((const long long*)ei)[pos]);
    return clampN(((const int*)ei)[pos]);
}

static __device__ __forceinline__ uint32_t pack2(__nv_bfloat16 a, __nv_bfloat16 b) {
    return (uint32_t)__bfloat16_as_ushort(a) | ((uint32_t)__bfloat16_as_ushort(b) << 16);
}
static __device__ __forceinline__ void split2(float2 u, uint32_t& hi, uint32_t& lo) {
    __nv_bfloat16 hx = __float2bfloat16(u.x);
    __nv_bfloat16 hy = __float2bfloat16(u.y);
    hi = pack2(hx, hy);
    lo = pack2(__float2bfloat16(u.x - __bfloat162float(hx)),
               __float2bfloat16(u.y - __bfloat162float(hy)));
}

// mma.sync m16n8k16 row.col f32.bf16.bf16.f32 (legacy tensor path, sm_80+)
#define MMA_BF16(d, a, b0v, b1v) \
    asm volatile("mma.sync.aligned.m16n8k16.row.col.f32.bf16.bf16.f32 " \
        "{%0,%1,%2,%3}, {%4,%5,%6,%7}, {%8,%9}, {%0,%1,%2,%3};" \
        : "+f"((d)[0]), "+f"((d)[1]), "+f"((d)[2]), "+f"((d)[3]) \
        : "r"((a)[0]), "r"((a)[1]), "r"((a)[2]), "r"((a)[3]), "r"(b0v), "r"(b1v))

// ---------------- dtype detection ----------------
__global__ void k_detect(const int* __restrict__ ei32) {
    if (threadIdx.x == 0 && blockIdx.x == 0) {
        int allzero = 1;
        #pragma unroll 1
        for (int i = 0; i < 64; i++)
            if (ei32[2 * i + 1] != 0) { allzero = 0; break; }
        g_is64 = allzero;
    }
}

// ---------------- CSR build ----------------
__global__ void k_zero_deg() {
    int i = blockIdx.x * blockDim.x + threadIdx.x;
    if (i < NN) g_deg[i] = 0;
}

__global__ void k_count(const void* __restrict__ ei) {
    int e = blockIdx.x * blockDim.x + threadIdx.x;
    if (e < NE) {
        int dst = load_idx(ei, (size_t)NE + e, g_is64);
        atomicAdd(&g_deg[dst], 1);
    }
}

__global__ __launch_bounds__(1024) void k_scan_local() {
    __shared__ int ws[32];
    int b = blockIdx.x, t = threadIdx.x;
    int base = b * SCAN_CHUNK + t * 4;
    int v[4];
    #pragma unroll
    for (int c = 0; c < 4; c++) v[c] = (base + c < NN) ? g_deg[base + c] : 0;
    int s = v[0] + v[1] + v[2] + v[3];
    int x = s;
    #pragma unroll
    for (int o = 1; o < 32; o <<= 1) {
        int y = __shfl_up_sync(0xffffffffu, x, o);
        if ((t & 31) >= o) x += y;
    }
    if ((t & 31) == 31) ws[t >> 5] = x;
    __syncthreads();
    if (t < 32) {
        int w = ws[t];
        #pragma unroll
        for (int o = 1; o < 32; o <<= 1) {
            int y = __shfl_up_sync(0xffffffffu, w, o);
            if (t >= o) w += y;
        }
        ws[t] = w;
    }
    __syncthreads();
    int incl = x + ((t >= 32) ? ws[(t >> 5) - 1] : 0);
    int run = incl - s;
    #pragma unroll
    for (int c = 0; c < 4; c++) {
        if (base + c < NN) g_off[base + c] = run;
        run += v[c];
    }
    if (t == 1023) g_bsum[b] = incl;
}

__global__ void k_scan_bsum() {
    int t = threadIdx.x;
    int v = (t < NBLK) ? g_bsum[t] : 0;
    int x = v;
    #pragma unroll
    for (int o = 1; o < 32; o <<= 1) {
        int y = __shfl_up_sync(0xffffffffu, x, o);
        if (t >= o) x += y;
    }
    if (t < NBLK) g_bpre[t] = x - v;
    if (t == 31) g_off[NN] = x;
}

__global__ void k_scan_add() {
    int i = blockIdx.x * blockDim.x + threadIdx.x;
    if (i < NN) {
        int o = g_off[i] + g_bpre[i / SCAN_CHUNK];
        g_off[i] = o;
        g_cur[i] = o;
    }
}

__global__ void k_scatter(const void* __restrict__ ei, const float* __restrict__ ea) {
    int e = blockIdx.x * blockDim.x + threadIdx.x;
    if (e < NE) {
        int is64 = g_is64;
        int s = load_idx(ei, (size_t)e, is64);
        int d = load_idx(ei, (size_t)NE + e, is64);
        int p = atomicAdd(&g_cur[d], 1);
        if (p >= 0 && p < NE) {
            g_src[p] = s;
            g_w[p]   = ea[e];
        }
    }
}

// ---------------- GraphConv max aggregation (warp per node, unroll-4) ------
template <int F, int XSEL>
__global__ void k_gc_agg(const float* __restrict__ xext) {
    const float* __restrict__ x = SB<XSEL>(xext);
    float* __restrict__ agg = g_bufA;
    int node = (blockIdx.x * blockDim.x + threadIdx.x) >> 5;
    int lane = threadIdx.x & 31;
    if (node >= NN) return;
    int beg = g_off[node], end = g_off[node + 1];
    if constexpr (F == 128) {
        float4 mx = make_float4(-INFINITY, -INFINITY, -INFINITY, -INFINITY);
        int j = beg;
        for (; j + 3 < end; j += 4) {
            int   s0 = g_src[j],   s1 = g_src[j+1], s2 = g_src[j+2], s3 = g_src[j+3];
            float w0 = g_w[j],     w1 = g_w[j+1],   w2 = g_w[j+2],   w3 = g_w[j+3];
            float4 v0 = *(const float4*)&x[(size_t)s0 * 128 + lane * 4];
            float4 v1 = *(const float4*)&x[(size_t)s1 * 128 + lane * 4];
            float4 v2 = *(const float4*)&x[(size_t)s2 * 128 + lane * 4];
            float4 v3 = *(const float4*)&x[(size_t)s3 * 128 + lane * 4];
            mx.x = fmaxf(mx.x, fmaxf(fmaxf(v0.x*w0, v1.x*w1), fmaxf(v2.x*w2, v3.x*w3)));
            mx.y = fmaxf(mx.y, fmaxf(fmaxf(v0.y*w0, v1.y*w1), fmaxf(v2.y*w2, v3.y*w3)));
            mx.z = fmaxf(mx.z, fmaxf(fmaxf(v0.z*w0, v1.z*w1), fmaxf(v2.z*w2, v3.z*w3)));
            mx.w = fmaxf(mx.w, fmaxf(fmaxf(v0.w*w0, v1.w*w1), fmaxf(v2.w*w2, v3.w*w3)));
        }
        for (; j < end; j++) {
            int s = g_src[j];
            float w = g_w[j];
            float4 v = *(const float4*)&x[(size_t)s * 128 + lane * 4];
            mx.x = fmaxf(mx.x, v.x * w);
            mx.y = fmaxf(mx.y, v.y * w);
            mx.z = fmaxf(mx.z, v.z * w);
            mx.w = fmaxf(mx.w, v.w * w);
        }
        if (beg == end) mx = make_float4(0.f, 0.f, 0.f, 0.f);
        *(float4*)&agg[(size_t)node * 128 + lane * 4] = mx;
    } else {
        float mx = -INFINITY;
        int j = beg;
        for (; j + 3 < end; j += 4) {
            int   s0 = g_src[j],   s1 = g_src[j+1], s2 = g_src[j+2], s3 = g_src[j+3];
            float w0 = g_w[j],     w1 = g_w[j+1],   w2 = g_w[j+2],   w3 = g_w[j+3];
            float a = x[(size_t)s0 * 32 + lane] * w0;
            float b = x[(size_t)s1 * 32 + lane] * w1;
            float c = x[(size_t)s2 * 32 + lane] * w2;
            float d = x[(size_t)s3 * 32 + lane] * w3;
            mx = fmaxf(mx, fmaxf(fmaxf(a, b), fmaxf(c, d)));
        }
        for (; j < end; j++) mx = fmaxf(mx, x[(size_t)g_src[j] * 32 + lane] * g_w[j]);
        agg[(size_t)node * 32 + lane] = (beg == end) ? 0.f : mx;
    }
}

// ---------------- mma.sync bf16 GEMM: xl/xr (N=256), 3-term split ----------
// C[M,256] = A[M,KDIM] @ W (+bias); z=0 -> Wl/g_bufA, z=1 -> Wr/g_bufB.
// A,W split into bf16 hi+lo in-kernel; D += Ahi*Whi + Ahi*Wlo + Alo*Whi.
// Block 256 thr (8 warps, 4m x 2n), tile 128x128, BK=32. (R12-validated)
template <int KDIM, int ASEL>
__global__ __launch_bounds__(256)
void k_mma_gemm(const float* __restrict__ Bl, const float* __restrict__ biasl,
                const float* __restrict__ Br, const float* __restrict__ biasr) {
    constexpr int KW = 16;                      // BK/2 words per row
    __shared__ uint32_t Ah[128][KW + 1], Al[128][KW + 1];
    __shared__ uint32_t Bh[128][KW + 1], Bq[128][KW + 1];

    const float* __restrict__ A = SB<ASEL>((const float*)0);
    const float* __restrict__ W  = blockIdx.z ? Br : Bl;
    const float* __restrict__ bi = blockIdx.z ? biasr : biasl;
    float* __restrict__ C        = blockIdx.z ? g_bufB : g_bufA;

    int tid = threadIdx.x;
    int wid = tid >> 5, lane = tid & 31;
    int warp_m = wid & 3, warp_n = wid >> 2;
    int m0 = blockIdx.y * 128;
    int n0 = blockIdx.x * 128;
    int lg = lane >> 2, lq = lane & 3;          // group row / quad

    float acc[2][8][4];
    #pragma unroll
    for (int mt = 0; mt < 2; mt++)
        #pragma unroll
        for (int nt = 0; nt < 8; nt++)
            #pragma unroll
            for (int c = 0; c < 4; c++) acc[mt][nt][c] = 0.f;

    for (int kb = 0; kb < KDIM; kb += 32) {
        // load A tile (128 rows x 16 words), convert fp32 -> bf16 hi/lo
        #pragma unroll
        for (int i = 0; i < 8; i++) {
            int idx = tid + i * 256;            // 0..2047
            int r = idx >> 4, w = idx & 15;
            int row = m0 + r;
            float2 u = make_float2(0.f, 0.f);
            if (row < NN) u = ((const float2*)&A[(size_t)row * KDIM + kb])[w];
            split2(u, Ah[r][w], Al[r][w]);
        }
        // load W tile: Bh[n][w] = W[kb+2w][n0+n], W[kb+2w+1][n0+n]
        #pragma unroll
        for (int i = 0; i < 8; i++) {
            int idx = tid + i * 256;
            int n = idx & 127, w = idx >> 7;
            int k0 = kb + w * 2;
            float2 u = make_float2(W[(size_t)k0 * 256 + n0 + n],
                                   W[(size_t)(k0 + 1) * 256 + n0 + n]);
            split2(u, Bh[n][w], Bq[n][w]);
        }
        __syncthreads();

        #pragma unroll
        for (int ks = 0; ks < 2; ks++) {
            int ws = ks * 8;
            uint32_t ah[2][4], al[2][4];
            #pragma unroll
            for (int mt = 0; mt < 2; mt++) {
                int r = warp_m * 32 + mt * 16 + lg;
                ah[mt][0] = Ah[r][ws + lq];     ah[mt][1] = Ah[r + 8][ws + lq];
                ah[mt][2] = Ah[r][ws + 4 + lq]; ah[mt][3] = Ah[r + 8][ws + 4 + lq];
                al[mt][0] = Al[r][ws + lq];     al[mt][1] = Al[r + 8][ws + lq];
                al[mt][2] = Al[r][ws + 4 + lq]; al[mt][3] = Al[r + 8][ws + 4 + lq];
            }
            #pragma unroll
            for (int nt = 0; nt < 8; nt++) {
                int cb = warp_n * 64 + nt * 8 + lg;
                uint32_t bh0 = Bh[cb][ws + lq], bh1 = Bh[cb][ws + 4 + lq];
                uint32_t bq0 = Bq[cb][ws + lq], bq1 = Bq[cb][ws + 4 + lq];
                #pragma unroll
                for (int mt = 0; mt < 2; mt++) {
                    MMA_BF16(acc[mt][nt], ah[mt], bh0, bh1);
                    MMA_BF16(acc[mt][nt], ah[mt], bq0, bq1);
                    MMA_BF16(acc[mt][nt], al[mt], bh0, bh1);
                }
            }
        }
        __syncthreads();
    }

    // epilogue: add bias, store
    #pragma unroll
    for (int nt = 0; nt < 8; nt++) {
        int col = n0 + warp_n * 64 + nt * 8 + lq * 2;
        float b0 = bi[col], b1 = bi[col + 1];
        #pragma unroll
        for (int mt = 0; mt < 2; mt++) {
            int r0 = m0 + warp_m * 32 + mt * 16 + lg;
            if (r0 < NN) {
                float2 o = make_float2(acc[mt][nt][0] + b0, acc[mt][nt][1] + b1);
                *(float2*)&C[(size_t)r0 * 256 + col] = o;
            }
            if (r0 + 8 < NN) {
                float2 o = make_float2(acc[mt][nt][2] + b0, acc[mt][nt][3] + b1);
                *(float2*)&C[(size_t)(r0 + 8) * 256 + col] = o;
            }
        }
    }
}

// ---------------- mma.sync bf16 GEMM, N=32 (dual-A, optional relu) ---------
// C[M,32] = act(A1@B1 (+ A2@B2) + bias); bf16 3-term split, in-kernel convert.
// 128 thr (4 warps = 4 m-slices of 32 rows), BK=32. (R15-validated, -22us)
template <int K, int A1SEL, bool DUAL, int A2SEL, bool RELU, int CSEL>
__global__ __launch_bounds__(128)
void k_mma_n32(const float* __restrict__ A1e, const float* __restrict__ B1,
               const float* __restrict__ A2e, const float* __restrict__ B2,
               const float* __restrict__ bias, float* __restrict__ Ce) {
    __shared__ uint32_t A1h[128][17], A1l[128][17];
    __shared__ uint32_t A2h[DUAL ? 128 : 1][17], A2l[DUAL ? 128 : 1][17];
    __shared__ uint32_t B1h[32][17], B1q[32][17];
    __shared__ uint32_t B2h[DUAL ? 32 : 1][17], B2q[DUAL ? 32 : 1][17];

    const float* __restrict__ A1 = SB<A1SEL>(A1e);
    const float* __restrict__ A2 = SB<A2SEL>(A2e);
    float* __restrict__ C = SBo<CSEL>(Ce);

    int tid = threadIdx.x;
    int wid = tid >> 5, lane = tid & 31;
    int m0 = blockIdx.x * 128;
    int lg = lane >> 2, lq = lane & 3;

    float acc[2][4][4];
    #pragma unroll
    for (int mt = 0; mt < 2; mt++)
        #pragma unroll
        for (int nt = 0; nt < 4; nt++)
            #pragma unroll
            for (int c = 0; c < 4; c++) acc[mt][nt][c] = 0.f;

    for (int kb = 0; kb < K; kb += 32) {
        #pragma unroll
        for (int i = 0; i < 16; i++) {
            int idx = tid + i * 128;
            int r = idx >> 4, w = idx & 15;
            int row = m0 + r;
            float2 u1 = make_float2(0.f, 0.f);
            if (row < NN) u1 = *(const float2*)&A1[(size_t)row * K + kb + 2 * w];
            split2(u1, A1h[r][w], A1l[r][w]);
            if constexpr (DUAL) {
                float2 u2 = make_float2(0.f, 0.f);
                if (row < NN) u2 = *(const float2*)&A2[(size_t)row * K + kb + 2 * w];
                split2(u2, A2h[r][w], A2l[r][w]);
            }
        }
        #pragma unroll
        for (int i = 0; i < 4; i++) {
            int idx = tid + i * 128;
            int n = idx >> 4, w = idx & 15;
            float2 u1 = make_float2(B1[(size_t)(kb + 2 * w) * 32 + n],
                                    B1[(size_t)(kb + 2 * w + 1) * 32 + n]);
            split2(u1, B1h[n][w], B1q[n][w]);
            if constexpr (DUAL) {
                float2 u2 = make_float2(B2[(size_t)(kb + 2 * w) * 32 + n],
                                        B2[(size_t)(kb + 2 * w + 1) * 32 + n]);
                split2(u2, B2h[n][w], B2q[n][w]);
            }
        }
        __syncthreads();

        #pragma unroll
        for (int ks = 0; ks < 2; ks++) {
            int ws = ks * 8;
            uint32_t ah[2][4], al[2][4];
            #pragma unroll
            for (int mt = 0; mt < 2; mt++) {
                int r = wid * 32 + mt * 16 + lg;
                ah[mt][0] = A1h[r][ws + lq];     ah[mt][1] = A1h[r + 8][ws + lq];
                ah[mt][2] = A1h[r][ws + 4 + lq]; ah[mt][3] = A1h[r + 8][ws + 4 + lq];
                al[mt][0] = A1l[r][ws + lq];     al[mt][1] = A1l[r + 8][ws + lq];
                al[mt][2] = A1l[r][ws + 4 + lq]; al[mt][3] = A1l[r + 8][ws + 4 + lq];
            }
            #pragma unroll
            for (int nt = 0; nt < 4; nt++) {
                int cb = nt * 8 + lg;
                uint32_t bh0 = B1h[cb][ws + lq], bh1 = B1h[cb][ws + 4 + lq];
                uint32_t bq0 = B1q[cb][ws + lq], bq1 = B1q[cb][ws + 4 + lq];
                #pragma unroll
                for (int mt = 0; mt < 2; mt++) {
                    MMA_BF16(acc[mt][nt], ah[mt], bh0, bh1);
                    MMA_BF16(acc[mt][nt], ah[mt], bq0, bq1);
                    MMA_BF16(acc[mt][nt], al[mt], bh0, bh1);
                }
            }
            if constexpr (DUAL) {
                #pragma unroll
                for (int mt = 0; mt < 2; mt++) {
                    int r = wid * 32 + mt * 16 + lg;
                    ah[mt][0] = A2h[r][ws + lq];     ah[mt][1] = A2h[r + 8][ws + lq];
                    ah[mt][2] = A2h[r][ws + 4 + lq]; ah[mt][3] = A2h[r + 8][ws + 4 + lq];
                    al[mt][0] = A2l[r][ws + lq];     al[mt][1] = A2l[r + 8][ws + lq];
                    al[mt][2] = A2l[r][ws + 4 + lq]; al[mt][3] = A2l[r + 8][ws + 4 + lq];
                }
                #pragma unroll
                for (int nt = 0; nt < 4; nt++) {
                    int cb = nt * 8 + lg;
                    uint32_t bh0 = B2h[cb][ws + lq], bh1 = B2h[cb][ws + 4 + lq];
                    uint32_t bq0 = B2q[cb][ws + lq], bq1 = B2q[cb][ws + 4 + lq];
                    #pragma unroll
                    for (int mt = 0; mt < 2; mt++) {
                        MMA_BF16(acc[mt][nt], ah[mt], bh0, bh1);
                        MMA_BF16(acc[mt][nt], ah[mt], bq0, bq1);
                        MMA_BF16(acc[mt][nt], al[mt], bh0, bh1);
                    }
                }
            }
        }
        __syncthreads();
    }

    #pragma unroll
    for (int nt = 0; nt < 4; nt++) {
        int col = nt * 8 + lq * 2;
        float b0 = bias[col], b1 = bias[col + 1];
        #pragma unroll
        for (int mt = 0; mt < 2; mt++) {
            int r0 = m0 + wid * 32 + mt * 16 + lg;
            float v0 = acc[mt][nt][0] + b0, v1 = acc[mt][nt][1] + b1;
            float v2 = acc[mt][nt][2] + b0, v3 = acc[mt][nt][3] + b1;
            if constexpr (RELU) {
                v0 = fmaxf(v0, 0.f); v1 = fmaxf(v1, 0.f);
                v2 = fmaxf(v2, 0.f); v3 = fmaxf(v3, 0.f);
            }
            if (r0 < NN)     *(float2*)&C[(size_t)r0 * 32 + col]       = make_float2(v0, v1);
            if (r0 + 8 < NN) *(float2*)&C[(size_t)(r0 + 8) * 32 + col] = make_float2(v2, v3);
        }
    }
}

// ---------------- GATv2: warp per node, 2-edge branch-free online softmax --
template <int OSEL>
__global__ void k_gat(const float* __restrict__ att, const float* __restrict__ bias) {
    const float* __restrict__ xl = g_bufA;
    const float* __restrict__ xr = g_bufB;
    float* __restrict__ out = SBo<OSEL>((float*)0);

    int node = (blockIdx.x * blockDim.x + threadIdx.x) >> 5;
    int lane = threadIdx.x & 31;
    if (node >= NN) return;
    int base = (lane >> 2) * 32 + (lane & 3) * 8;

    float4 at0 = *(const float4*)&att[base];
    float4 at1 = *(const float4*)&att[base + 4];
    float4 xr0 = *(const float4*)&xr[(size_t)node * 256 + base];
    float4 xr1 = *(const float4*)&xr[(size_t)node * 256 + base + 4];

    float m = -INFINITY, d = 0.f;
    float4 acc0 = make_float4(0.f, 0.f, 0.f, 0.f);
    float4 acc1 = make_float4(0.f, 0.f, 0.f, 0.f);

    int beg = g_off[node], end = g_off[node + 1];
    int T = end - beg + 1;
    int t = 0;
    for (; t + 1 < T; t += 2) {
        int i0 = beg + t, i1 = beg + t + 1;
        int s0 = g_src[i0];
        int s1 = (i1 < end) ? g_src[i1] : node;
        float4 a0 = *(const float4*)&xl[(size_t)s0 * 256 + base];
        float4 a1 = *(const float4*)&xl[(size_t)s0 * 256 + base + 4];
        float4 b0 = *(const float4*)&xl[(size_t)s1 * 256 + base];
        float4 b1 = *(const float4*)&xl[(size_t)s1 * 256 + base + 4];
        float sc0 = at0.x * lrelu(a0.x + xr0.x) + at0.y * lrelu(a0.y + xr0.y)
                  + at0.z * lrelu(a0.z + xr0.z) + at0.w * lrelu(a0.w + xr0.w)
                  + at1.x * lrelu(a1.x + xr1.x) + at1.y * lrelu(a1.y + xr1.y)
                  + at1.z * lrelu(a1.z + xr1.z) + at1.w * lrelu(a1.w + xr1.w);
        float sc1 = at0.x * lrelu(b0.x + xr0.x) + at0.y * lrelu(b0.y + xr0.y)
                  + at0.z * lrelu(b0.z + xr0.z) + at0.w * lrelu(b0.w + xr0.w)
                  + at1.x * lrelu(b1.x + xr1.x) + at1.y * lrelu(b1.y + xr1.y)
                  + at1.z * lrelu(b1.z + xr1.z) + at1.w * lrelu(b1.w + xr1.w);
        sc0 += __shfl_xor_sync(0xffffffffu, sc0, 1);
        sc0 += __shfl_xor_sync(0xffffffffu, sc0, 2);
        sc1 += __shfl_xor_sync(0xffffffffu, sc1, 1);
        sc1 += __shfl_xor_sync(0xffffffffu, sc1, 2);
        float nm = fmaxf(m, fmaxf(sc0, sc1));
        float r  = __expf(m - nm);
        float p0 = __expf(sc0 - nm);
        float p1 = __expf(sc1 - nm);
        d = d * r + p0 + p1;
        acc0.x = acc0.x * r + p0 * a0.x + p1 * b0.x;
        acc0.y = acc0.y * r + p0 * a0.y + p1 * b0.y;
        acc0.z = acc0.z * r + p0 * a0.z + p1 * b0.z;
        acc0.w = acc0.w * r + p0 * a0.w + p1 * b0.w;
        acc1.x = acc1.x * r + p0 * a1.x + p1 * b1.x;
        acc1.y = acc1.y * r + p0 * a1.y + p1 * b1.y;
        acc1.z = acc1.z * r + p0 * a1.z + p1 * b1.z;
        acc1.w = acc1.w * r + p0 * a1.w + p1 * b1.w;
        m = nm;
    }
    if (t < T) {
        int i0 = beg + t;
        int s = (i0 < end) ? g_src[i0] : node;
        float4 a0 = *(const float4*)&xl[(size_t)s * 256 + base];
        float4 a1 = *(const float4*)&xl[(size_t)s * 256 + base + 4];
        float sc = at0.x * lrelu(a0.x + xr0.x) + at0.y * lrelu(a0.y + xr0.y)
                 + at0.z * lrelu(a0.z + xr0.z) + at0.w * lrelu(a0.w + xr0.w)
                 + at1.x * lrelu(a1.x + xr1.x) + at1.y * lrelu(a1.y + xr1.y)
                 + at1.z * lrelu(a1.z + xr1.z) + at1.w * lrelu(a1.w + xr1.w);
        sc += __shfl_xor_sync(0xffffffffu, sc, 1);
        sc += __shfl_xor_sync(0xffffffffu, sc, 2);
        float nm = fmaxf(m, sc);
        float r  = __expf(m - nm);
        float p  = __expf(sc - nm);
        d = d * r + p;
        acc0.x = acc0.x * r + p * a0.x; acc0.y = acc0.y * r + p * a0.y;
        acc0.z = acc0.z * r + p * a0.z; acc0.w = acc0.w * r + p * a0.w;
        acc1.x = acc1.x * r + p * a1.x; acc1.y = acc1.y * r + p * a1.y;
        acc1.z = acc1.z * r + p * a1.z; acc1.w = acc1.w * r + p * a1.w;
    }

    float inv = 1.f / d;
    float4 b0 = *(const float4*)&bias[base];
    float4 b1 = *(const float4*)&bias[base + 4];
    float4 o0, o1;
    o0.x = elu(acc0.x * inv + b0.x); o0.y = elu(acc0.y * inv + b0.y);
    o0.z = elu(acc0.z * inv + b0.z); o0.w = elu(acc0.w * inv + b0.w);
    o1.x = elu(acc1.x * inv + b1.x); o1.y = elu(acc1.y * inv + b1.y);
    o1.z = elu(acc1.z * inv + b1.z); o1.w = elu(acc1.w * inv + b1.w);
    *(float4*)&out[(size_t)node * 256 + base]     = o0;
    *(float4*)&out[(size_t)node * 256 + base + 4] = o1;
}

// ---------------- launch ----------------
extern "C" void kernel_launch(void* const* d_in, const int* in_sizes, int n_in,
                              void* d_out, int out_size) {
    const float* x       = (const float*)d_in[0];
    const void*  ei      = d_in[1];
    const float* ea      = (const float*)d_in[2];
    const float* W_rel1  = (const float*)d_in[3];
    const float* b_rel1  = (const float*)d_in[4];
    const float* W_root1 = (const float*)d_in[5];
    const float* W_rel2  = (const float*)d_in[6];
    const float* b_rel2  = (const float*)d_in[7];
    const float* W_root2 = (const float*)d_in[8];
    const float* Wl1     = (const float*)d_in[9];
    const float* bl1     = (const float*)d_in[10];
    const float* Wr1     = (const float*)d_in[11];
    const float* br1     = (const float*)d_in[12];
    const float* att1    = (const float*)d_in[13];
    const float* bias1   = (const float*)d_in[14];
    const float* Wl2     = (const float*)d_in[15];
    const float* bl2     = (const float*)d_in[16];
    const float* Wr2     = (const float*)d_in[17];
    const float* br2     = (const float*)d_in[18];
    const float* att2    = (const float*)d_in[19];
    const float* bias2   = (const float*)d_in[20];
    const float* W_lin   = (const float*)d_in[21];
    const float* b_lin   = (const float*)d_in[22];
    float*       out     = (float*)d_out;

    const int MT = (NN + 127) / 128;   // 391 M-tiles
    dim3 gmma(2, MT, 2);

    // dtype detection + CSR build
    k_detect<<<1, 32>>>((const int*)ei);
    k_zero_deg<<<(NN + 255) / 256, 256>>>();
    k_count<<<(NE + 255) / 256, 256>>>(ei);
    k_scan_local<<<NBLK, 1024>>>();
    k_scan_bsum<<<1, 32>>>();
    k_scan_add<<<(NN + 255) / 256, 256>>>();
    k_scatter<<<(NE + 255) / 256, 256>>>(ei, ea);

    // GraphConv 1: agg(x) -> g_bufA; h1 = relu(agg@W_rel1 + x@W_root1 + b)
    k_gc_agg<128, -1><<<(NN + 7) / 8, 256>>>(x);
    k_mma_n32<128, 0, true, -1, true, 2><<<MT, 128>>>(
        (const float*)0, W_rel1, x, W_root1, b_rel1, (float*)0);

    // GraphConv 2: agg(h1) -> g_bufA; h2 = relu(agg@W_rel2 + h1@W_root2 + b)
    k_gc_agg<32, 2><<<(NN + 7) / 8, 256>>>((const float*)0);
    k_mma_n32<32, 0, true, 2, true, 3><<<MT, 128>>>(
        (const float*)0, W_rel2, (const float*)0, W_root2, b_rel2, (float*)0);

    // GATv2 1: xl/xr via mma bf16-split, in-kernel convert (A = h2, K=32)
    k_mma_gemm<32, 3><<<gmma, 256>>>(Wl1, bl1, Wr1, br1);
    k_gat<4><<<(NN + 7) / 8, 256>>>(att1, bias1);

    // GATv2 2: xl/xr via mma bf16-split, in-kernel convert (A = h3, K=256)
    k_mma_gemm<256, 4><<<gmma, 256>>>(Wl2, bl2, Wr2, br2);
    k_gat<5><<<(NN + 7) / 8, 256>>>(att2, bias2);

    // Final linear: out = h4 @ W_lin + b_lin
    k_mma_n32<256, 5, false, -1, false, -1><<<MT, 128>>>(
        (const float*)0, W_lin, (const float*)0, (const float*)0, b_lin, out);
}